// round 2
// baseline (speedup 1.0000x reference)
#include <cuda_runtime.h>
#include <math.h>

#define BB 8
#define NN 4096
#define DD 768
#define EE 8
#define SS 2
#define ES 16
#define FF 3072
#define NTOK (BB*NN)   /* 32768 */

typedef unsigned long long ull;

/* ------------ scratch (no allocations allowed) ------------ */
__device__ float g_part0[NTOK*ES];
__device__ float g_part1[NTOK*ES];
__device__ float g_logits[NTOK*ES];
__device__ float g_disp[NTOK*ES];
__device__ float g_comb[NTOK*ES];
__device__ float g_xs[BB*ES*DD];
__device__ float g_h[EE*ES*FF];
__device__ float g_ys[BB*ES*DD];

/* ------------ f32x2 helpers (FFMA2 — only reachable via PTX) ------------ */
__device__ __forceinline__ ull fma2(ull a, ull b, ull c) {
    ull d;
    asm("fma.rn.f32x2 %0, %1, %2, %3;" : "=l"(d) : "l"(a), "l"(b), "l"(c));
    return d;
}
__device__ __forceinline__ ull dup2(float x) {
    ull r;
    asm("mov.b64 %0, {%1, %1};" : "=l"(r) : "f"(x));
    return r;
}
__device__ __forceinline__ ull pack2(float x, float y) {
    ull r;
    asm("mov.b64 %0, {%1, %2};" : "=l"(r) : "f"(x), "f"(y));
    return r;
}
__device__ __forceinline__ float2 unpack2(ull a) {
    float2 t;
    asm("mov.b64 {%0, %1}, %2;" : "=f"(t.x), "=f"(t.y) : "l"(a));
    return t;
}

__device__ __forceinline__ float gelu_exact(float v) {
    return 0.5f * v * (1.0f + erff(v * 0.70710678118654752440f));
}

/* ------------ K0: zero xs/ys accumulators ------------ */
__global__ void k0_zero() {
    int i = blockIdx.x * 1024 + threadIdx.x;   /* grid 96 x 1024 = 98304 */
    g_xs[i] = 0.0f;
    g_ys[i] = 0.0f;
}

/* ------------ K1: logits partials  [32768,768]x[768,16], split in 2 K-halves
   grid (64 token-blocks, 2 halves), 128 threads.
   Each thread: 4 tokens x 16 slots, acc as 4x8 f32x2. ------------ */
__global__ void __launch_bounds__(128) k1_logits(const float* __restrict__ x,
                                                 const float* __restrict__ phi) {
    extern __shared__ float sm[];
    float* x_sh   = sm;              /* [512][33] pitch 33 -> conflict-free LDS */
    float* phi_sh = sm + 512 * 33;   /* [32][16] */
    const int tid     = threadIdx.x;
    const int tokBase = blockIdx.x * 512;
    const int half    = blockIdx.y;
    const int kbase   = half * 384;

    ull acc[4][8];
#pragma unroll
    for (int p = 0; p < 4; p++)
#pragma unroll
        for (int j = 0; j < 8; j++) acc[p][j] = 0ull;

    for (int c = 0; c < 12; c++) {
        const int k0 = kbase + c * 32;
        /* stage x: 512 tokens x 32 k, coalesced float4, conflict-free STS */
#pragma unroll
        for (int it = 0; it < 32; it++) {
            int idx = tid + 128 * it;          /* 0..4095 */
            int row = idx >> 3, q = idx & 7;
            float4 v = *(const float4*)(x + (size_t)(tokBase + row) * DD + k0 + q * 4);
            float* dst = &x_sh[row * 33 + q * 4];
            dst[0] = v.x; dst[1] = v.y; dst[2] = v.z; dst[3] = v.w;
        }
        /* stage phi chunk: contiguous 512 floats */
#pragma unroll
        for (int it = 0; it < 4; it++) {
            int idx = tid + 128 * it;
            phi_sh[idx] = phi[k0 * ES + idx];
        }
        __syncthreads();
#pragma unroll 8
        for (int kk = 0; kk < 32; kk++) {
            ull xd[4];
#pragma unroll
            for (int p = 0; p < 4; p++)
                xd[p] = dup2(x_sh[(tid + 128 * p) * 33 + kk]);
#pragma unroll
            for (int j = 0; j < 8; j++) {
                ull ph = *(const ull*)&phi_sh[kk * ES + 2 * j];  /* broadcast LDS.64 */
#pragma unroll
                for (int p = 0; p < 4; p++)
                    acc[p][j] = fma2(xd[p], ph, acc[p][j]);
            }
        }
        __syncthreads();
    }

    float* outb = half ? g_part1 : g_part0;
#pragma unroll
    for (int p = 0; p < 4; p++) {
        int tg = tokBase + tid + 128 * p;
        float4* o = (float4*)&outb[(size_t)tg * ES];
#pragma unroll
        for (int j2 = 0; j2 < 4; j2++) {
            float2 a = unpack2(acc[p][2 * j2]);
            float2 b = unpack2(acc[p][2 * j2 + 1]);
            o[j2] = make_float4(a.x, a.y, b.x, b.y);
        }
    }
}

/* ------------ K2a: sum partials + dispatch softmax (over 16 slots) ------------ */
__global__ void __launch_bounds__(256) k2a_dispatch() {
    int t = blockIdx.x * 256 + threadIdx.x;    /* grid 128 */
    const float4* p0 = (const float4*)&g_part0[(size_t)t * ES];
    const float4* p1 = (const float4*)&g_part1[(size_t)t * ES];
    float v[16];
#pragma unroll
    for (int i = 0; i < 4; i++) {
        float4 a = p0[i], b = p1[i];
        v[4 * i + 0] = a.x + b.x; v[4 * i + 1] = a.y + b.y;
        v[4 * i + 2] = a.z + b.z; v[4 * i + 3] = a.w + b.w;
    }
    float m = v[0];
#pragma unroll
    for (int e = 1; e < 16; e++) m = fmaxf(m, v[e]);
    float ex[16], s = 0.0f;
#pragma unroll
    for (int e = 0; e < 16; e++) { ex[e] = expf(v[e] - m); s += ex[e]; }
    float inv = 1.0f / s;
    float4* lo = (float4*)&g_logits[(size_t)t * ES];
    float4* dd = (float4*)&g_disp[(size_t)t * ES];
#pragma unroll
    for (int i = 0; i < 4; i++) {
        lo[i] = make_float4(v[4*i], v[4*i+1], v[4*i+2], v[4*i+3]);
        dd[i] = make_float4(ex[4*i]*inv, ex[4*i+1]*inv, ex[4*i+2]*inv, ex[4*i+3]*inv);
    }
}

/* ------------ K2b: combine softmax (over N=4096 tokens), one block per (slot,b) ------------ */
__device__ __forceinline__ float warp_max(float v) {
#pragma unroll
    for (int o = 16; o; o >>= 1) v = fmaxf(v, __shfl_xor_sync(0xffffffffu, v, o));
    return v;
}
__device__ __forceinline__ float warp_sum(float v) {
#pragma unroll
    for (int o = 16; o; o >>= 1) v += __shfl_xor_sync(0xffffffffu, v, o);
    return v;
}
__global__ void __launch_bounds__(256) k2b_combine() {
    const int e = blockIdx.x, b = blockIdx.y, tid = threadIdx.x;
    const int wid = tid >> 5, lane = tid & 31;
    __shared__ float red[8];
    __shared__ float bc;
    const float* base = g_logits + (size_t)b * NN * ES + e;
    float v[16];
#pragma unroll
    for (int i = 0; i < 16; i++) v[i] = base[(size_t)(tid + 256 * i) * ES];
    float m = -1e30f;
#pragma unroll
    for (int i = 0; i < 16; i++) m = fmaxf(m, v[i]);
    m = warp_max(m);
    if (lane == 0) red[wid] = m;
    __syncthreads();
    if (tid == 0) {
        float t = red[0];
        for (int w = 1; w < 8; w++) t = fmaxf(t, red[w]);
        bc = t;
    }
    __syncthreads();
    m = bc;
    __syncthreads();
    float ex[16], s = 0.0f;
#pragma unroll
    for (int i = 0; i < 16; i++) { ex[i] = expf(v[i] - m); s += ex[i]; }
    s = warp_sum(s);
    if (lane == 0) red[wid] = s;
    __syncthreads();
    if (tid == 0) {
        float t = 0.0f;
        for (int w = 0; w < 8; w++) t += red[w];
        bc = t;
    }
    __syncthreads();
    float inv = 1.0f / bc;
    float* ob = g_comb + (size_t)b * NN * ES + e;
#pragma unroll
    for (int i = 0; i < 16; i++) ob[(size_t)(tid + 256 * i) * ES] = ex[i] * inv;
}

/* ------------ K3: xs[b,slot,d] = sum_n disp[b,n,slot]*x[b,n,d]
   grid (16 n-chunks, 8 b), 256 threads; thread owns 3 d's x 16 slots ------------ */
__global__ void __launch_bounds__(256) k3_xs(const float* __restrict__ x) {
    __shared__ float dsh[64 * ES];
    const int chunk = blockIdx.x, b = blockIdx.y, tid = threadIdx.x;
    ull acc[8][3];
#pragma unroll
    for (int j = 0; j < 8; j++)
#pragma unroll
        for (int d = 0; d < 3; d++) acc[j][d] = 0ull;

    for (int g = 0; g < 4; g++) {
        const int n0 = chunk * 256 + g * 64;
        ((float4*)dsh)[tid] = ((const float4*)&g_disp[(size_t)(b * NN + n0) * ES])[tid];
        __syncthreads();
#pragma unroll 4
        for (int nn = 0; nn < 64; nn++) {
            const float* xr = x + (size_t)(b * NN + n0 + nn) * DD + tid;
            ull xd0 = dup2(xr[0]);
            ull xd1 = dup2(xr[256]);
            ull xd2 = dup2(xr[512]);
#pragma unroll
            for (int j = 0; j < 8; j++) {
                ull c2 = *(const ull*)&dsh[nn * ES + 2 * j];   /* broadcast */
                acc[j][0] = fma2(c2, xd0, acc[j][0]);
                acc[j][1] = fma2(c2, xd1, acc[j][1]);
                acc[j][2] = fma2(c2, xd2, acc[j][2]);
            }
        }
        __syncthreads();
    }
#pragma unroll
    for (int j = 0; j < 8; j++)
#pragma unroll
        for (int dd = 0; dd < 3; dd++) {
            float2 a = unpack2(acc[j][dd]);
            int d = tid + 256 * dd;
            atomicAdd(&g_xs[(size_t)(b * ES + 2 * j) * DD + d], a.x);
            atomicAdd(&g_xs[(size_t)(b * ES + 2 * j + 1) * DD + d], a.y);
        }
}

/* ------------ K4: h = gelu(xs @ w1 + b1), per-expert 16x768x3072
   grid (24 f-tiles, 8 experts), 128 threads; row r = b*2+s ------------ */
__global__ void __launch_bounds__(128) k4_ffn1(const float* __restrict__ w1,
                                               const float* __restrict__ b1) {
    __shared__ float xsh[DD * ES];   /* [d][r], 48KB */
    const int e = blockIdx.y, f0 = blockIdx.x * 128, tid = threadIdx.x;
#pragma unroll
    for (int r = 0; r < 16; r++)
#pragma unroll
        for (int dq = 0; dq < 6; dq++) {
            int d = tid + 128 * dq;
            xsh[d * ES + r] = g_xs[(size_t)((r >> 1) * ES + e * 2 + (r & 1)) * DD + d];
        }
    __syncthreads();
    const int f = f0 + tid;
    ull acc[8];
#pragma unroll
    for (int j = 0; j < 8; j++) acc[j] = 0ull;
    const float* wp = w1 + (size_t)e * DD * FF + f;
#pragma unroll 4
    for (int d = 0; d < DD; d++) {
        ull wd = dup2(__ldg(wp + (size_t)d * FF));
#pragma unroll
        for (int j = 0; j < 8; j++)
            acc[j] = fma2(*(const ull*)&xsh[d * ES + 2 * j], wd, acc[j]);
    }
    const float bv = b1[e * FF + f];
#pragma unroll
    for (int j = 0; j < 8; j++) {
        float2 a = unpack2(acc[j]);
        g_h[(size_t)(e * ES + 2 * j) * FF + f]     = gelu_exact(a.x + bv);
        g_h[(size_t)(e * ES + 2 * j + 1) * FF + f] = gelu_exact(a.y + bv);
    }
}

/* ------------ K5: ys = h @ w2 + b2, per-expert 16x3072x768, k split 4 ways
   grid (6 d-tiles, 8 experts, 4 k-chunks), 128 threads ------------ */
__global__ void __launch_bounds__(128) k5_ffn2(const float* __restrict__ w2,
                                               const float* __restrict__ b2) {
    __shared__ float hsh[DD * ES];   /* [kk][r], 48KB */
    const int e = blockIdx.y, d0 = blockIdx.x * 128, z = blockIdx.z, tid = threadIdx.x;
    const int k0 = z * 768;
#pragma unroll
    for (int r = 0; r < 16; r++)
#pragma unroll
        for (int kq = 0; kq < 6; kq++) {
            int kk = tid + 128 * kq;
            hsh[kk * ES + r] = g_h[(size_t)(e * ES + r) * FF + k0 + kk];
        }
    __syncthreads();
    const int d = d0 + tid;
    ull acc[8];
#pragma unroll
    for (int j = 0; j < 8; j++) acc[j] = 0ull;
    const float* wp = w2 + (size_t)e * FF * DD + (size_t)k0 * DD + d;
#pragma unroll 4
    for (int kk = 0; kk < 768; kk++) {
        ull wd = dup2(__ldg(wp + (size_t)kk * DD));
#pragma unroll
        for (int j = 0; j < 8; j++)
            acc[j] = fma2(*(const ull*)&hsh[kk * ES + 2 * j], wd, acc[j]);
    }
    const float bv = (z == 0) ? b2[e * DD + d] : 0.0f;
#pragma unroll
    for (int j = 0; j < 8; j++) {      /* r = 2j -> (b=j,s=0); r = 2j+1 -> (b=j,s=1) */
        float2 a = unpack2(acc[j]);
        atomicAdd(&g_ys[(size_t)(j * ES + e * 2 + 0) * DD + d], a.x + bv);
        atomicAdd(&g_ys[(size_t)(j * ES + e * 2 + 1) * DD + d], a.y + bv);
    }
}

/* ------------ K6: y[b,n,d] = sum_slot comb[b,n,slot]*ys[b,slot,d]
   grid (64 n-chunks, 8 b), 256 threads; ys column held in registers ------------ */
__global__ void __launch_bounds__(256) k6_out(float* __restrict__ y) {
    __shared__ float csh[64 * ES];
    const int chunk = blockIdx.x, b = blockIdx.y, tid = threadIdx.x;
    ull ysr[8][3];
#pragma unroll
    for (int j = 0; j < 8; j++)
#pragma unroll
        for (int dd = 0; dd < 3; dd++) {
            int d = tid + 256 * dd;
            ysr[j][dd] = pack2(g_ys[(size_t)(b * ES + 2 * j) * DD + d],
                               g_ys[(size_t)(b * ES + 2 * j + 1) * DD + d]);
        }
    ((float4*)csh)[tid] = ((const float4*)&g_comb[(size_t)(b * NN + chunk * 64) * ES])[tid];
    __syncthreads();
#pragma unroll 2
    for (int tok = 0; tok < 64; tok++) {
        ull c2[8];
#pragma unroll
        for (int j = 0; j < 8; j++) c2[j] = *(const ull*)&csh[tok * ES + 2 * j];
        float* yo = y + (size_t)(b * NN + chunk * 64 + tok) * DD + tid;
#pragma unroll
        for (int dd = 0; dd < 3; dd++) {
            ull a = 0ull;
#pragma unroll
            for (int j = 0; j < 8; j++) a = fma2(c2[j], ysr[j][dd], a);
            float2 t = unpack2(a);
            yo[256 * dd] = t.x + t.y;
        }
    }
}

/* ------------ launch ------------ */
extern "C" void kernel_launch(void* const* d_in, const int* in_sizes, int n_in,
                              void* d_out, int out_size) {
    const float* x   = (const float*)d_in[0];
    const float* phi = (const float*)d_in[1];
    const float* w1  = (const float*)d_in[2];
    const float* b1  = (const float*)d_in[3];
    const float* w2  = (const float*)d_in[4];
    const float* b2  = (const float*)d_in[5];
    float* y = (float*)d_out;

    cudaFuncSetAttribute(k1_logits, cudaFuncAttributeMaxDynamicSharedMemorySize, 69632);

    k0_zero<<<96, 1024>>>();
    k1_logits<<<dim3(64, 2), 128, 69632>>>(x, phi);
    k2a_dispatch<<<128, 256>>>();
    k2b_combine<<<dim3(16, 8), 256>>>();
    k3_xs<<<dim3(16, 8), 256>>>(x);
    k4_ffn1<<<dim3(24, 8), 128>>>(w1, b1);
    k5_ffn2<<<dim3(6, 8, 4), 128>>>(w2, b2);
    k6_out<<<dim3(64, 8), 256>>>(y);
}

// round 5
// speedup vs baseline: 2.1187x; 2.1187x over previous
#include <cuda_runtime.h>
#include <math.h>

#define BB 8
#define NN 4096
#define DD 768
#define EE 8
#define ES 16
#define FF 3072
#define NTOK (BB*NN)     /* 32768 */
#define PSZ  (NTOK*ES)   /* 524288 */

typedef unsigned long long ull;

/* ---------------- scratch (allocation-free, 16B-aligned) ---------------- */
__device__ __align__(16) float  g_part[4*PSZ];     /* k1 logits partials */
__device__ __align__(16) float  g_logits[PSZ];
__device__ __align__(16) float  g_disp[PSZ];
__device__ __align__(16) float  g_comb[PSZ];
__device__ __align__(16) float2 g_cpart[128*16];
__device__ __align__(16) float2 g_cms[128];
__device__ __align__(16) float  g_xsp[256*16*768]; /* k3 partials */
__device__ __align__(16) float  g_xs[BB*ES*DD];
__device__ __align__(16) float  g_h1p[8*EE*ES*FF]; /* k4 partials */
__device__ __align__(16) float  g_h[EE*ES*FF];
__device__ __align__(16) float  g_ysp[24*EE*ES*DD];/* k5 partials */
__device__ __align__(16) float  g_ys[BB*ES*DD];

/* ---------------- f32x2 helpers ---------------- */
__device__ __forceinline__ ull fma2(ull a, ull b, ull c) {
    ull d; asm("fma.rn.f32x2 %0, %1, %2, %3;" : "=l"(d) : "l"(a), "l"(b), "l"(c)); return d;
}
__device__ __forceinline__ ull dup2(float x) {
    ull r; asm("mov.b64 %0, {%1, %1};" : "=l"(r) : "f"(x)); return r;
}
__device__ __forceinline__ float2 unpack2(ull a) {
    float2 t; asm("mov.b64 {%0, %1}, %2;" : "=f"(t.x), "=f"(t.y) : "l"(a)); return t;
}
__device__ __forceinline__ float gelu_exact(float v) {
    return 0.5f * v * (1.0f + erff(v * 0.70710678118654752440f));
}
__device__ __forceinline__ float warp_max(float v) {
#pragma unroll
    for (int o = 16; o; o >>= 1) v = fmaxf(v, __shfl_xor_sync(0xffffffffu, v, o));
    return v;
}
__device__ __forceinline__ float warp_sum(float v) {
#pragma unroll
    for (int o = 16; o; o >>= 1) v += __shfl_xor_sync(0xffffffffu, v, o);
    return v;
}

/* ================ K1: logits partials =================
   grid (64 token-blocks, 4 k-chunks of 192), 256 thr, 2 tokens/thread. */
__global__ void __launch_bounds__(256) k1_logits(const float* __restrict__ x,
                                                 const float* __restrict__ phi) {
    extern __shared__ float sm[];
    float* xsh = sm;              /* [512][33] pitch-33, conflict-free */
    float* ph  = sm + 512 * 33;   /* [192][16] */
    const int tid = threadIdx.x;
    const int tokBase = blockIdx.x * 512;
    const int k0 = blockIdx.y * 192;

    for (int i = tid; i < 768; i += 256)
        ((float4*)ph)[i] = ((const float4*)(phi + (size_t)k0 * ES))[i];

    ull acc[2][8];
#pragma unroll
    for (int p = 0; p < 2; p++)
#pragma unroll
        for (int j = 0; j < 8; j++) acc[p][j] = 0ull;

    for (int sc = 0; sc < 6; sc++) {
        const int kk0 = k0 + sc * 32;
        __syncthreads();
#pragma unroll
        for (int i = 0; i < 16; i++) {
            int idx = tid + 256 * i;            /* 0..4095 : (token, f4) */
            int t = idx >> 3, q = idx & 7;
            float4 v = *(const float4*)(x + (size_t)(tokBase + t) * DD + kk0 + q * 4);
            float* dst = &xsh[t * 33 + q * 4];  /* pitch 33: scalar STS (alignment!) */
            dst[0] = v.x; dst[1] = v.y; dst[2] = v.z; dst[3] = v.w;
        }
        __syncthreads();
#pragma unroll 4
        for (int kk = 0; kk < 32; kk++) {
            ull xd0 = dup2(xsh[tid * 33 + kk]);
            ull xd1 = dup2(xsh[(tid + 256) * 33 + kk]);
            const float* pr = &ph[(sc * 32 + kk) * ES];
#pragma unroll
            for (int j = 0; j < 8; j++) {
                ull p2 = *(const ull*)&pr[2 * j];
                acc[0][j] = fma2(xd0, p2, acc[0][j]);
                acc[1][j] = fma2(xd1, p2, acc[1][j]);
            }
        }
    }
    float* outb = g_part + (size_t)blockIdx.y * PSZ;
#pragma unroll
    for (int p = 0; p < 2; p++) {
        int t = tokBase + tid + 256 * p;
        float4* o = (float4*)&outb[(size_t)t * ES];
#pragma unroll
        for (int j2 = 0; j2 < 4; j2++) {
            float2 a = unpack2(acc[p][2 * j2]);
            float2 b = unpack2(acc[p][2 * j2 + 1]);
            o[j2] = make_float4(a.x, a.y, b.x, b.y);
        }
    }
}

/* ================ K2a: sum partials, dispatch softmax, combine partial-reduce ===== */
__global__ void __launch_bounds__(256) k2a_dispatch() {
    __shared__ float2 wred[8 * 16];
    const int tid = threadIdx.x;
    const int t = blockIdx.x * 256 + tid;
    const int wid = tid >> 5, lane = tid & 31;
    float v[16];
#pragma unroll
    for (int i = 0; i < 16; i++) v[i] = 0.0f;
#pragma unroll
    for (int c = 0; c < 4; c++) {
        const float4* p = (const float4*)(g_part + (size_t)c * PSZ + (size_t)t * ES);
#pragma unroll
        for (int i = 0; i < 4; i++) {
            float4 a = p[i];
            v[4*i+0] += a.x; v[4*i+1] += a.y; v[4*i+2] += a.z; v[4*i+3] += a.w;
        }
    }
    float m = v[0];
#pragma unroll
    for (int i = 1; i < 16; i++) m = fmaxf(m, v[i]);
    float ex[16], s = 0.0f;
#pragma unroll
    for (int i = 0; i < 16; i++) { ex[i] = expf(v[i] - m); s += ex[i]; }
    float inv = 1.0f / s;
    float4* lo = (float4*)&g_logits[(size_t)t * ES];
    float4* dd = (float4*)&g_disp[(size_t)t * ES];
#pragma unroll
    for (int i = 0; i < 4; i++) {
        lo[i] = make_float4(v[4*i], v[4*i+1], v[4*i+2], v[4*i+3]);
        dd[i] = make_float4(ex[4*i]*inv, ex[4*i+1]*inv, ex[4*i+2]*inv, ex[4*i+3]*inv);
    }
#pragma unroll
    for (int sl = 0; sl < 16; sl++) {
        float wm = warp_max(v[sl]);
        float ws = warp_sum(expf(v[sl] - wm));
        if (lane == 0) wred[wid * 16 + sl] = make_float2(wm, ws);
    }
    __syncthreads();
    if (tid < 16) {
        float gm = -1e30f;
#pragma unroll
        for (int w = 0; w < 8; w++) gm = fmaxf(gm, wred[w * 16 + tid].x);
        float gs = 0.0f;
#pragma unroll
        for (int w = 0; w < 8; w++) {
            float2 p = wred[w * 16 + tid];
            gs += expf(p.x - gm) * p.y;
        }
        g_cpart[blockIdx.x * 16 + tid] = make_float2(gm, gs);
    }
}

/* ================ K2c: reduce combine partials ===== */
__global__ void k2c_reduce() {
    int tid = threadIdx.x;               /* 0..127 = (b,slot) */
    int b = tid >> 4, sl = tid & 15;
    float gm = -1e30f;
#pragma unroll
    for (int c = 0; c < 16; c++) gm = fmaxf(gm, g_cpart[(b * 16 + c) * 16 + sl].x);
    float gs = 0.0f;
#pragma unroll
    for (int c = 0; c < 16; c++) {
        float2 p = g_cpart[(b * 16 + c) * 16 + sl];
        gs += expf(p.x - gm) * p.y;
    }
    g_cms[tid] = make_float2(gm, 1.0f / gs);
}

/* ================ K2d: combine weights ===== */
__global__ void __launch_bounds__(256) k2d_combine() {
    __shared__ float2 csh[16];
    const int tid = threadIdx.x;
    const int t = blockIdx.x * 256 + tid;
    const int b = blockIdx.x >> 4;
    if (tid < 16) csh[tid] = g_cms[b * 16 + tid];
    __syncthreads();
    const float4* lo = (const float4*)&g_logits[(size_t)t * ES];
    float4* ob = (float4*)&g_comb[(size_t)t * ES];
#pragma unroll
    for (int i = 0; i < 4; i++) {
        float4 v = lo[i];
        float4 r;
        r.x = expf(v.x - csh[4*i+0].x) * csh[4*i+0].y;
        r.y = expf(v.y - csh[4*i+1].x) * csh[4*i+1].y;
        r.z = expf(v.z - csh[4*i+2].x) * csh[4*i+2].y;
        r.w = expf(v.w - csh[4*i+3].x) * csh[4*i+3].y;
        ob[i] = r;
    }
}

/* ================ K3: xs partials  grid(32 chunks, 8 b), 192 thr ===== */
__global__ void __launch_bounds__(192) k3_xs(const float* __restrict__ x) {
    __shared__ float2 dsh[128 * 16];
    const int chunk = blockIdx.x, b = blockIdx.y, tid = threadIdx.x;
    const int n0 = chunk * 128;
    for (int i = tid; i < 512; i += 192) {
        float4 v = ((const float4*)g_disp)[(size_t)(b * NN + n0) * 4 + i];
        int t = i >> 2, sq = i & 3;
        float2* d = &dsh[t * 16 + sq * 4];
        d[0] = make_float2(v.x, v.x); d[1] = make_float2(v.y, v.y);
        d[2] = make_float2(v.z, v.z); d[3] = make_float2(v.w, v.w);
    }
    __syncthreads();
    ull acc[16][2];
#pragma unroll
    for (int s = 0; s < 16; s++) { acc[s][0] = 0ull; acc[s][1] = 0ull; }
    const float* xb = x + (size_t)(b * NN + n0) * DD + tid * 4;
    for (int g = 0; g < 128; g += 8) {
        float4 xv[8];
#pragma unroll
        for (int u = 0; u < 8; u++) xv[u] = *(const float4*)(xb + (size_t)(g + u) * DD);
#pragma unroll
        for (int u = 0; u < 8; u++) {
            ull l = *(ull*)&xv[u].x, h = *(ull*)&xv[u].z;
            const float2* dr = &dsh[(g + u) * 16];
#pragma unroll
            for (int s = 0; s < 16; s++) {
                ull c = *(const ull*)&dr[s];
                acc[s][0] = fma2(c, l, acc[s][0]);
                acc[s][1] = fma2(c, h, acc[s][1]);
            }
        }
    }
    float* op = g_xsp + (size_t)(b * 32 + chunk) * 16 * DD + tid * 4;
#pragma unroll
    for (int s = 0; s < 16; s++) {
        float2 a = unpack2(acc[s][0]), c = unpack2(acc[s][1]);
        *(float4*)(op + (size_t)s * DD) = make_float4(a.x, a.y, c.x, c.y);
    }
}

/* ================ K3r: reduce 32 chunks -> g_xs ===== */
__global__ void __launch_bounds__(256) k3r_reduce() {
    int o4 = blockIdx.x * 256 + threadIdx.x;      /* 24576 float4 */
    int d4 = o4 % 192, rest = o4 / 192;
    int sl = rest & 15, b = rest >> 4;
    float4 s = make_float4(0.f, 0.f, 0.f, 0.f);
#pragma unroll 8
    for (int c = 0; c < 32; c++) {
        float4 v = ((const float4*)g_xsp)[((size_t)(b * 32 + c) * 16 + sl) * 192 + d4];
        s.x += v.x; s.y += v.y; s.z += v.z; s.w += v.w;
    }
    ((float4*)g_xs)[o4] = s;
}

/* ================ K4: FFN1 partials  grid(3 ftiles, 8 e, 8 dchunks), 256 thr ===== */
__global__ void __launch_bounds__(256) k4_ffn1(const float* __restrict__ w1) {
    __shared__ float2 xd[96 * 16];
    const int ft = blockIdx.x, e = blockIdx.y, dc = blockIdx.z, tid = threadIdx.x;
    const int dk0 = dc * 96;
    for (int i = tid; i < 1536; i += 256) {
        int ddv = i >> 4, r = i & 15;
        float v = g_xs[(size_t)((r >> 1) * 16 + e * 2 + (r & 1)) * DD + dk0 + ddv];
        xd[i] = make_float2(v, v);
    }
    __syncthreads();
    const int f = ft * 1024 + tid * 4;
    const float* wp = w1 + (size_t)e * DD * FF + (size_t)dk0 * FF + f;
    ull acc[16][2];
#pragma unroll
    for (int r = 0; r < 16; r++) { acc[r][0] = 0ull; acc[r][1] = 0ull; }
    for (int d = 0; d < 96; d += 4) {
        float4 wv[4];
#pragma unroll
        for (int u = 0; u < 4; u++) wv[u] = *(const float4*)(wp + (size_t)(d + u) * FF);
#pragma unroll
        for (int u = 0; u < 4; u++) {
            ull l = *(ull*)&wv[u].x, h = *(ull*)&wv[u].z;
            const float2* xr = &xd[(d + u) * 16];
#pragma unroll
            for (int r = 0; r < 16; r++) {
                ull c = *(const ull*)&xr[r];
                acc[r][0] = fma2(c, l, acc[r][0]);
                acc[r][1] = fma2(c, h, acc[r][1]);
            }
        }
    }
    float* op = g_h1p + (size_t)(dc * 8 + e) * 16 * FF + f;
#pragma unroll
    for (int r = 0; r < 16; r++) {
        float2 a = unpack2(acc[r][0]), c = unpack2(acc[r][1]);
        *(float4*)(op + (size_t)r * FF) = make_float4(a.x, a.y, c.x, c.y);
    }
}

/* ================ K4r: reduce 8 dchunks + bias + gelu -> g_h ===== */
__global__ void __launch_bounds__(256) k4r_reduce(const float* __restrict__ b1) {
    int o4 = blockIdx.x * 256 + threadIdx.x;     /* 98304 float4 */
    float4 s = make_float4(0.f, 0.f, 0.f, 0.f);
#pragma unroll
    for (int c = 0; c < 8; c++) {
        float4 v = ((const float4*)g_h1p)[(size_t)o4 + (size_t)c * 98304];
        s.x += v.x; s.y += v.y; s.z += v.z; s.w += v.w;
    }
    int f4 = o4 % 768;
    int e = o4 / (16 * 768);
    float4 bv = ((const float4*)b1)[e * 768 + f4];
    float4 r;
    r.x = gelu_exact(s.x + bv.x); r.y = gelu_exact(s.y + bv.y);
    r.z = gelu_exact(s.z + bv.z); r.w = gelu_exact(s.w + bv.w);
    ((float4*)g_h)[o4] = r;
}

/* ================ K5: FFN2 partials  grid(24 kchunks, 8 e), 192 thr ===== */
__global__ void __launch_bounds__(192) k5_ffn2(const float* __restrict__ w2) {
    __shared__ float2 hd[128 * 16];
    const int kc = blockIdx.x, e = blockIdx.y, tid = threadIdx.x;
    const int k0 = kc * 128;
    for (int i = tid; i < 2048; i += 192) {
        int kk = i >> 4, r = i & 15;
        float v = g_h[(size_t)(e * 16 + r) * FF + k0 + kk];
        hd[i] = make_float2(v, v);
    }
    __syncthreads();
    const int d4 = tid * 4;
    const float* wp = w2 + (size_t)e * FF * DD + (size_t)k0 * DD + d4;
    ull acc[16][2];
#pragma unroll
    for (int r = 0; r < 16; r++) { acc[r][0] = 0ull; acc[r][1] = 0ull; }
    for (int kk = 0; kk < 128; kk += 4) {
        float4 wv[4];
#pragma unroll
        for (int u = 0; u < 4; u++) wv[u] = *(const float4*)(wp + (size_t)(kk + u) * DD);
#pragma unroll
        for (int u = 0; u < 4; u++) {
            ull l = *(ull*)&wv[u].x, h = *(ull*)&wv[u].z;
            const float2* hr = &hd[(kk + u) * 16];
#pragma unroll
            for (int r = 0; r < 16; r++) {
                ull c = *(const ull*)&hr[r];
                acc[r][0] = fma2(c, l, acc[r][0]);
                acc[r][1] = fma2(c, h, acc[r][1]);
            }
        }
    }
    float* op = g_ysp + (size_t)(kc * 8 + e) * 16 * DD + d4;
#pragma unroll
    for (int r = 0; r < 16; r++) {
        float2 a = unpack2(acc[r][0]), c = unpack2(acc[r][1]);
        *(float4*)(op + (size_t)r * DD) = make_float4(a.x, a.y, c.x, c.y);
    }
}

/* ================ K5r: reduce 24 kchunks + bias -> g_ys ===== */
__global__ void __launch_bounds__(256) k5r_reduce(const float* __restrict__ b2) {
    int o4 = blockIdx.x * 256 + threadIdx.x;    /* 24576 float4 */
    int d4 = o4 % 192, rest = o4 / 192;
    int sl = rest & 15, b = rest >> 4;
    int e = sl >> 1;
    int r = b * 2 + (sl & 1);
    float4 s = make_float4(0.f, 0.f, 0.f, 0.f);
#pragma unroll 8
    for (int c = 0; c < 24; c++) {
        float4 v = ((const float4*)g_ysp)[((size_t)(c * 8 + e) * 16 + r) * 192 + d4];
        s.x += v.x; s.y += v.y; s.z += v.z; s.w += v.w;
    }
    float4 bv = ((const float4*)b2)[e * 192 + d4];
    ((float4*)g_ys)[o4] = make_float4(s.x + bv.x, s.y + bv.y, s.z + bv.z, s.w + bv.w);
}

/* ================ K6: y = comb @ ys  grid(64 n-chunks, 8 b), 256 thr ===== */
__global__ void __launch_bounds__(256) k6_out(float* __restrict__ y) {
    __shared__ float csh[64 * ES];
    const int chunk = blockIdx.x, b = blockIdx.y, tid = threadIdx.x;
    ull ysr[8][3];
#pragma unroll
    for (int j = 0; j < 8; j++)
#pragma unroll
        for (int dd = 0; dd < 3; dd++) {
            int d = tid + 256 * dd;
            float a = g_ys[(size_t)(b * 16 + 2 * j) * DD + d];
            float c = g_ys[(size_t)(b * 16 + 2 * j + 1) * DD + d];
            ull r; asm("mov.b64 %0, {%1, %2};" : "=l"(r) : "f"(a), "f"(c));
            ysr[j][dd] = r;
        }
    ((float4*)csh)[tid] = ((const float4*)&g_comb[(size_t)(b * NN + chunk * 64) * ES])[tid];
    __syncthreads();
#pragma unroll 2
    for (int tok = 0; tok < 64; tok++) {
        ull c2[8];
#pragma unroll
        for (int j = 0; j < 8; j++) c2[j] = *(const ull*)&csh[tok * ES + 2 * j];
        float* yo = y + (size_t)(b * NN + chunk * 64 + tok) * DD + tid;
#pragma unroll
        for (int dd = 0; dd < 3; dd++) {
            ull a = 0ull;
#pragma unroll
            for (int j = 0; j < 8; j++) a = fma2(c2[j], ysr[j][dd], a);
            float2 t = unpack2(a);
            yo[256 * dd] = t.x + t.y;
        }
    }
}

/* ---------------- launch ---------------- */
extern "C" void kernel_launch(void* const* d_in, const int* in_sizes, int n_in,
                              void* d_out, int out_size) {
    const float* x   = (const float*)d_in[0];
    const float* phi = (const float*)d_in[1];
    const float* w1  = (const float*)d_in[2];
    const float* b1  = (const float*)d_in[3];
    const float* w2  = (const float*)d_in[4];
    const float* b2  = (const float*)d_in[5];
    float* y = (float*)d_out;

    cudaFuncSetAttribute(k1_logits, cudaFuncAttributeMaxDynamicSharedMemorySize, 81920);

    k1_logits<<<dim3(64, 4), 256, 79872>>>(x, phi);
    k2a_dispatch<<<128, 256>>>();
    k2c_reduce<<<1, 128>>>();
    k2d_combine<<<128, 256>>>();
    k3_xs<<<dim3(32, 8), 192>>>(x);
    k3r_reduce<<<96, 256>>>();
    k4_ffn1<<<dim3(3, 8, 8), 256>>>(w1);
    k4r_reduce<<<384, 256>>>(b1);
    k5_ffn2<<<dim3(24, 8), 192>>>(w2);
    k5r_reduce<<<96, 256>>>(b2);
    k6_out<<<dim3(64, 8), 256>>>(y);
}

// round 6
// speedup vs baseline: 2.1858x; 1.0317x over previous
#include <cuda_runtime.h>
#include <math.h>

#define BB 8
#define NN 4096
#define DD 768
#define EE 8
#define ES 16
#define FF 3072
#define NTOK (BB*NN)     /* 32768 */
#define PSZ  (NTOK*ES)   /* 524288 */

typedef unsigned long long ull;

/* ---------------- scratch (allocation-free, 16B-aligned) ---------------- */
__device__ __align__(16) float  g_part[4*PSZ];     /* k1 logits partials */
__device__ __align__(16) float  g_logits[PSZ];
__device__ __align__(16) float2 g_cpart[128*16];   /* per-(chunk,slot) combine partials */
__device__ __align__(16) float  g_xsp[256*16*768]; /* k3 partials */
__device__ __align__(16) float  g_xs[BB*ES*DD];
__device__ __align__(16) float  g_h1p[8*EE*ES*FF]; /* k4 partials */
__device__ __align__(16) float  g_h[EE*ES*FF];
__device__ __align__(16) float  g_ysp[32*EE*ES*DD];/* k5 partials */
__device__ __align__(16) float  g_ys[BB*ES*DD];

/* ---------------- f32x2 helpers ---------------- */
__device__ __forceinline__ ull fma2(ull a, ull b, ull c) {
    ull d; asm("fma.rn.f32x2 %0, %1, %2, %3;" : "=l"(d) : "l"(a), "l"(b), "l"(c)); return d;
}
__device__ __forceinline__ ull dup2(float x) {
    ull r; asm("mov.b64 %0, {%1, %1};" : "=l"(r) : "f"(x)); return r;
}
__device__ __forceinline__ float2 unpack2(ull a) {
    float2 t; asm("mov.b64 {%0, %1}, %2;" : "=f"(t.x), "=f"(t.y) : "l"(a)); return t;
}
__device__ __forceinline__ float gelu_exact(float v) {
    return 0.5f * v * (1.0f + erff(v * 0.70710678118654752440f));
}
__device__ __forceinline__ float warp_max(float v) {
#pragma unroll
    for (int o = 16; o; o >>= 1) v = fmaxf(v, __shfl_xor_sync(0xffffffffu, v, o));
    return v;
}
__device__ __forceinline__ float warp_sum(float v) {
#pragma unroll
    for (int o = 16; o; o >>= 1) v += __shfl_xor_sync(0xffffffffu, v, o);
    return v;
}

/* ================ K1: logits partials  grid(64 tokblocks, 4 kchunks), 256 thr ===== */
__global__ void __launch_bounds__(256) k1_logits(const float* __restrict__ x,
                                                 const float* __restrict__ phi) {
    extern __shared__ float sm[];
    float* xsh = sm;              /* [512][33] pitch-33 */
    float* ph  = sm + 512 * 33;   /* [192][16] */
    const int tid = threadIdx.x;
    const int tokBase = blockIdx.x * 512;
    const int k0 = blockIdx.y * 192;

    for (int i = tid; i < 768; i += 256)
        ((float4*)ph)[i] = ((const float4*)(phi + (size_t)k0 * ES))[i];

    ull acc[2][8];
#pragma unroll
    for (int p = 0; p < 2; p++)
#pragma unroll
        for (int j = 0; j < 8; j++) acc[p][j] = 0ull;

    for (int sc = 0; sc < 6; sc++) {
        const int kk0 = k0 + sc * 32;
        __syncthreads();
#pragma unroll
        for (int i = 0; i < 16; i++) {
            int idx = tid + 256 * i;
            int t = idx >> 3, q = idx & 7;
            float4 v = *(const float4*)(x + (size_t)(tokBase + t) * DD + kk0 + q * 4);
            float* dst = &xsh[t * 33 + q * 4];   /* scalar STS: pitch-33 alignment */
            dst[0] = v.x; dst[1] = v.y; dst[2] = v.z; dst[3] = v.w;
        }
        __syncthreads();
#pragma unroll 4
        for (int kk = 0; kk < 32; kk++) {
            ull xd0 = dup2(xsh[tid * 33 + kk]);
            ull xd1 = dup2(xsh[(tid + 256) * 33 + kk]);
            const float* pr = &ph[(sc * 32 + kk) * ES];
#pragma unroll
            for (int j = 0; j < 8; j++) {
                ull p2 = *(const ull*)&pr[2 * j];
                acc[0][j] = fma2(xd0, p2, acc[0][j]);
                acc[1][j] = fma2(xd1, p2, acc[1][j]);
            }
        }
    }
    float* outb = g_part + (size_t)blockIdx.y * PSZ;
#pragma unroll
    for (int p = 0; p < 2; p++) {
        int t = tokBase + tid + 256 * p;
        float4* o = (float4*)&outb[(size_t)t * ES];
#pragma unroll
        for (int j2 = 0; j2 < 4; j2++) {
            float2 a = unpack2(acc[p][2 * j2]);
            float2 b = unpack2(acc[p][2 * j2 + 1]);
            o[j2] = make_float4(a.x, a.y, b.x, b.y);
        }
    }
}

/* ================ K2a: sum partials -> logits; combine partial-reduce ===== */
__global__ void __launch_bounds__(256) k2a_dispatch() {
    __shared__ float2 wred[8 * 16];
    const int tid = threadIdx.x;
    const int t = blockIdx.x * 256 + tid;
    const int wid = tid >> 5, lane = tid & 31;
    float v[16];
#pragma unroll
    for (int i = 0; i < 16; i++) v[i] = 0.0f;
#pragma unroll
    for (int c = 0; c < 4; c++) {
        const float4* p = (const float4*)(g_part + (size_t)c * PSZ + (size_t)t * ES);
#pragma unroll
        for (int i = 0; i < 4; i++) {
            float4 a = p[i];
            v[4*i+0] += a.x; v[4*i+1] += a.y; v[4*i+2] += a.z; v[4*i+3] += a.w;
        }
    }
    float4* lo = (float4*)&g_logits[(size_t)t * ES];
#pragma unroll
    for (int i = 0; i < 4; i++)
        lo[i] = make_float4(v[4*i], v[4*i+1], v[4*i+2], v[4*i+3]);
    /* combine partial (over this block's 256 tokens, all same b) per slot */
#pragma unroll
    for (int sl = 0; sl < 16; sl++) {
        float wm = warp_max(v[sl]);
        float ws = warp_sum(expf(v[sl] - wm));
        if (lane == 0) wred[wid * 16 + sl] = make_float2(wm, ws);
    }
    __syncthreads();
    if (tid < 16) {
        float gm = -1e30f;
#pragma unroll
        for (int w = 0; w < 8; w++) gm = fmaxf(gm, wred[w * 16 + tid].x);
        float gs = 0.0f;
#pragma unroll
        for (int w = 0; w < 8; w++) {
            float2 p = wred[w * 16 + tid];
            gs += expf(p.x - gm) * p.y;
        }
        g_cpart[blockIdx.x * 16 + tid] = make_float2(gm, gs);
    }
}

/* ================ K3: xs partials, dispatch softmax inline  grid(32,8), 192 thr ===== */
__global__ void __launch_bounds__(192) k3_xs(const float* __restrict__ x) {
    __shared__ float2 dsh[128 * 16];
    const int chunk = blockIdx.x, b = blockIdx.y, tid = threadIdx.x;
    const int n0 = chunk * 128;
    if (tid < 128) {
        const float4* lp = (const float4*)&g_logits[(size_t)(b * NN + n0 + tid) * ES];
        float v[16];
#pragma unroll
        for (int i = 0; i < 4; i++) {
            float4 a = lp[i];
            v[4*i] = a.x; v[4*i+1] = a.y; v[4*i+2] = a.z; v[4*i+3] = a.w;
        }
        float m = v[0];
#pragma unroll
        for (int i = 1; i < 16; i++) m = fmaxf(m, v[i]);
        float ex[16], s = 0.0f;
#pragma unroll
        for (int i = 0; i < 16; i++) { ex[i] = expf(v[i] - m); s += ex[i]; }
        float inv = 1.0f / s;
        float2* dr = &dsh[tid * 16];
#pragma unroll
        for (int i = 0; i < 16; i++) { float w = ex[i] * inv; dr[i] = make_float2(w, w); }
    }
    __syncthreads();
    ull acc[16][2];
#pragma unroll
    for (int s = 0; s < 16; s++) { acc[s][0] = 0ull; acc[s][1] = 0ull; }
    const float* xb = x + (size_t)(b * NN + n0) * DD + tid * 4;
    for (int g = 0; g < 128; g += 8) {
        float4 xv[8];
#pragma unroll
        for (int u = 0; u < 8; u++) xv[u] = *(const float4*)(xb + (size_t)(g + u) * DD);
#pragma unroll
        for (int u = 0; u < 8; u++) {
            ull l = *(ull*)&xv[u].x, h = *(ull*)&xv[u].z;
            const float2* dr = &dsh[(g + u) * 16];
#pragma unroll
            for (int s = 0; s < 16; s++) {
                ull c = *(const ull*)&dr[s];
                acc[s][0] = fma2(c, l, acc[s][0]);
                acc[s][1] = fma2(c, h, acc[s][1]);
            }
        }
    }
    float* op = g_xsp + (size_t)(b * 32 + chunk) * 16 * DD + tid * 4;
#pragma unroll
    for (int s = 0; s < 16; s++) {
        float2 a = unpack2(acc[s][0]), c = unpack2(acc[s][1]);
        *(float4*)(op + (size_t)s * DD) = make_float4(a.x, a.y, c.x, c.y);
    }
}

/* ================ K3r: reduce 32 chunks -> g_xs ===== */
__global__ void __launch_bounds__(256) k3r_reduce() {
    int o4 = blockIdx.x * 256 + threadIdx.x;
    int d4 = o4 % 192, rest = o4 / 192;
    int sl = rest & 15, b = rest >> 4;
    float4 s = make_float4(0.f, 0.f, 0.f, 0.f);
#pragma unroll 8
    for (int c = 0; c < 32; c++) {
        float4 v = ((const float4*)g_xsp)[((size_t)(b * 32 + c) * 16 + sl) * 192 + d4];
        s.x += v.x; s.y += v.y; s.z += v.z; s.w += v.w;
    }
    ((float4*)g_xs)[o4] = s;
}

/* ================ K4: FFN1 partials  grid(3,8,8), 256 thr, 8-wide MLP ===== */
__global__ void __launch_bounds__(256) k4_ffn1(const float* __restrict__ w1) {
    __shared__ float2 xd[96 * 16];
    const int ft = blockIdx.x, e = blockIdx.y, dc = blockIdx.z, tid = threadIdx.x;
    const int dk0 = dc * 96;
    for (int i = tid; i < 1536; i += 256) {
        int ddv = i >> 4, r = i & 15;
        float v = g_xs[(size_t)((r >> 1) * 16 + e * 2 + (r & 1)) * DD + dk0 + ddv];
        xd[i] = make_float2(v, v);
    }
    __syncthreads();
    const int f = ft * 1024 + tid * 4;
    const float* wp = w1 + (size_t)e * DD * FF + (size_t)dk0 * FF + f;
    ull acc[16][2];
#pragma unroll
    for (int r = 0; r < 16; r++) { acc[r][0] = 0ull; acc[r][1] = 0ull; }
    for (int d = 0; d < 96; d += 8) {
        float4 wv[8];
#pragma unroll
        for (int u = 0; u < 8; u++) wv[u] = *(const float4*)(wp + (size_t)(d + u) * FF);
#pragma unroll
        for (int u = 0; u < 8; u++) {
            ull l = *(ull*)&wv[u].x, h = *(ull*)&wv[u].z;
            const float2* xr = &xd[(d + u) * 16];
#pragma unroll
            for (int r = 0; r < 16; r++) {
                ull c = *(const ull*)&xr[r];
                acc[r][0] = fma2(c, l, acc[r][0]);
                acc[r][1] = fma2(c, h, acc[r][1]);
            }
        }
    }
    float* op = g_h1p + (size_t)(dc * 8 + e) * 16 * FF + f;
#pragma unroll
    for (int r = 0; r < 16; r++) {
        float2 a = unpack2(acc[r][0]), c = unpack2(acc[r][1]);
        *(float4*)(op + (size_t)r * FF) = make_float4(a.x, a.y, c.x, c.y);
    }
}

/* ================ K4r: reduce 8 dchunks + bias + gelu ===== */
__global__ void __launch_bounds__(256) k4r_reduce(const float* __restrict__ b1) {
    int o4 = blockIdx.x * 256 + threadIdx.x;
    float4 s = make_float4(0.f, 0.f, 0.f, 0.f);
#pragma unroll
    for (int c = 0; c < 8; c++) {
        float4 v = ((const float4*)g_h1p)[(size_t)o4 + (size_t)c * 98304];
        s.x += v.x; s.y += v.y; s.z += v.z; s.w += v.w;
    }
    int f4 = o4 % 768;
    int e = o4 / (16 * 768);
    float4 bv = ((const float4*)b1)[e * 768 + f4];
    float4 r;
    r.x = gelu_exact(s.x + bv.x); r.y = gelu_exact(s.y + bv.y);
    r.z = gelu_exact(s.z + bv.z); r.w = gelu_exact(s.w + bv.w);
    ((float4*)g_h)[o4] = r;
}

/* ================ K5: FFN2 partials  grid(32,8), 192 thr, 96-k chunks, 8-wide ===== */
__global__ void __launch_bounds__(192) k5_ffn2(const float* __restrict__ w2) {
    __shared__ float2 hd[96 * 16];
    const int kc = blockIdx.x, e = blockIdx.y, tid = threadIdx.x;
    const int k0 = kc * 96;
    for (int i = tid; i < 1536; i += 192) {
        int kk = i >> 4, r = i & 15;
        float v = g_h[(size_t)(e * 16 + r) * FF + k0 + kk];
        hd[i] = make_float2(v, v);
    }
    __syncthreads();
    const int d4 = tid * 4;
    const float* wp = w2 + (size_t)e * FF * DD + (size_t)k0 * DD + d4;
    ull acc[16][2];
#pragma unroll
    for (int r = 0; r < 16; r++) { acc[r][0] = 0ull; acc[r][1] = 0ull; }
    for (int kk = 0; kk < 96; kk += 8) {
        float4 wv[8];
#pragma unroll
        for (int u = 0; u < 8; u++) wv[u] = *(const float4*)(wp + (size_t)(kk + u) * DD);
#pragma unroll
        for (int u = 0; u < 8; u++) {
            ull l = *(ull*)&wv[u].x, h = *(ull*)&wv[u].z;
            const float2* hr = &hd[(kk + u) * 16];
#pragma unroll
            for (int r = 0; r < 16; r++) {
                ull c = *(const ull*)&hr[r];
                acc[r][0] = fma2(c, l, acc[r][0]);
                acc[r][1] = fma2(c, h, acc[r][1]);
            }
        }
    }
    float* op = g_ysp + (size_t)(kc * 8 + e) * 16 * DD + d4;
#pragma unroll
    for (int r = 0; r < 16; r++) {
        float2 a = unpack2(acc[r][0]), c = unpack2(acc[r][1]);
        *(float4*)(op + (size_t)r * DD) = make_float4(a.x, a.y, c.x, c.y);
    }
}

/* ================ K5r: reduce 32 kchunks + bias -> g_ys ===== */
__global__ void __launch_bounds__(256) k5r_reduce(const float* __restrict__ b2) {
    int o4 = blockIdx.x * 256 + threadIdx.x;
    int d4 = o4 % 192, rest = o4 / 192;
    int sl = rest & 15, b = rest >> 4;
    int e = sl >> 1;
    int r = b * 2 + (sl & 1);
    float4 s = make_float4(0.f, 0.f, 0.f, 0.f);
#pragma unroll 8
    for (int c = 0; c < 32; c++) {
        float4 v = ((const float4*)g_ysp)[((size_t)(c * 8 + e) * 16 + r) * 192 + d4];
        s.x += v.x; s.y += v.y; s.z += v.z; s.w += v.w;
    }
    float4 bv = ((const float4*)b2)[e * 192 + d4];
    ((float4*)g_ys)[o4] = make_float4(s.x + bv.x, s.y + bv.y, s.z + bv.z, s.w + bv.w);
}

/* ================ K6: combine norm + y = comb @ ys  grid(64,8), 256 thr ===== */
__global__ void __launch_bounds__(256) k6_out(float* __restrict__ y) {
    __shared__ float2 cms_sh[16];
    __shared__ float csh[64 * ES];
    const int chunk = blockIdx.x, b = blockIdx.y, tid = threadIdx.x;
    ull ysr[8][3];
#pragma unroll
    for (int j = 0; j < 8; j++)
#pragma unroll
        for (int dd = 0; dd < 3; dd++) {
            int d = tid + 256 * dd;
            float a = g_ys[(size_t)(b * 16 + 2 * j) * DD + d];
            float c = g_ys[(size_t)(b * 16 + 2 * j + 1) * DD + d];
            ull r; asm("mov.b64 %0, {%1, %2};" : "=l"(r) : "f"(a), "f"(c));
            ysr[j][dd] = r;
        }
    /* per-block (redundant) reduce of combine partials for this b */
    if (tid < 16) {
        float gm = -1e30f;
#pragma unroll
        for (int c = 0; c < 16; c++) gm = fmaxf(gm, g_cpart[(b * 16 + c) * 16 + tid].x);
        float gs = 0.0f;
#pragma unroll
        for (int c = 0; c < 16; c++) {
            float2 p = g_cpart[(b * 16 + c) * 16 + tid];
            gs += expf(p.x - gm) * p.y;
        }
        cms_sh[tid] = make_float2(gm, 1.0f / gs);
    }
    ((float4*)csh)[tid] = ((const float4*)&g_logits[(size_t)(b * NN + chunk * 64) * ES])[tid];
    __syncthreads();
    {   /* transform staged logits -> combine weights (4 per thread, slot-aligned) */
        int sl = (tid * 4) & 15;
        float4 v = ((float4*)csh)[tid];
        v.x = expf(v.x - cms_sh[sl+0].x) * cms_sh[sl+0].y;
        v.y = expf(v.y - cms_sh[sl+1].x) * cms_sh[sl+1].y;
        v.z = expf(v.z - cms_sh[sl+2].x) * cms_sh[sl+2].y;
        v.w = expf(v.w - cms_sh[sl+3].x) * cms_sh[sl+3].y;
        __syncthreads();
        ((float4*)csh)[tid] = v;
    }
    __syncthreads();
#pragma unroll 2
    for (int tok = 0; tok < 64; tok++) {
        ull c2[8];
#pragma unroll
        for (int j = 0; j < 8; j++) c2[j] = *(const ull*)&csh[tok * ES + 2 * j];
        float* yo = y + (size_t)(b * NN + chunk * 64 + tok) * DD + tid;
#pragma unroll
        for (int dd = 0; dd < 3; dd++) {
            ull a = 0ull;
#pragma unroll
            for (int j = 0; j < 8; j++) a = fma2(c2[j], ysr[j][dd], a);
            float2 t = unpack2(a);
            yo[256 * dd] = t.x + t.y;
        }
    }
}

/* ---------------- launch ---------------- */
extern "C" void kernel_launch(void* const* d_in, const int* in_sizes, int n_in,
                              void* d_out, int out_size) {
    const float* x   = (const float*)d_in[0];
    const float* phi = (const float*)d_in[1];
    const float* w1  = (const float*)d_in[2];
    const float* b1  = (const float*)d_in[3];
    const float* w2  = (const float*)d_in[4];
    const float* b2  = (const float*)d_in[5];
    float* y = (float*)d_out;

    cudaFuncSetAttribute(k1_logits, cudaFuncAttributeMaxDynamicSharedMemorySize, 81920);

    k1_logits<<<dim3(64, 4), 256, 79872>>>(x, phi);
    k2a_dispatch<<<128, 256>>>();
    k3_xs<<<dim3(32, 8), 192>>>(x);
    k3r_reduce<<<96, 256>>>();
    k4_ffn1<<<dim3(3, 8, 8), 256>>>(w1);
    k4r_reduce<<<384, 256>>>(b1);
    k5_ffn2<<<dim3(32, 8), 192>>>(w2);
    k5r_reduce<<<96, 256>>>(b2);
    k6_out<<<dim3(64, 8), 256>>>(y);
}